// round 7
// baseline (speedup 1.0000x reference)
#include <cuda_runtime.h>
#include <cstdint>
#include <math.h>

// Problem constants
#define P     48
#define FLEN  168
#define TCH   84     // t-chunk per CTA (2 chunks cover 168)
#define HIST  336
#define HOFF  288    // HIST - P

__device__ float g_G[P * FLEN];
__device__ float g_C[FLEN];
__device__ float g_lv;

typedef unsigned long long ull;

__device__ __forceinline__ ull pack2(float a, float b) {
    ull r; asm("mov.b64 %0, {%1, %2};" : "=l"(r) : "f"(a), "f"(b)); return r;
}
__device__ __forceinline__ ull ffma2(ull a, ull b, ull c) {
    ull d; asm("fma.rn.f32x2 %0, %1, %2, %3;" : "=l"(d) : "l"(a), "l"(b), "l"(c)); return d;
}

// ---------------------------------------------------------------------------
// Kernel 1: precompute affine map. Loop-carried dep kept in an 8-reg rotating
// window (single-FFMA critical path); smem reads have lag >= 5 (latency safe).
// ---------------------------------------------------------------------------
__global__ void precompute_kernel(const float* __restrict__ phi,
                                  const float* __restrict__ bias,
                                  const float* __restrict__ log_sigma2,
                                  const float* __restrict__ mu_p,
                                  const float* __restrict__ sigma_p) {
    __shared__ float h[P + 1][221];   // odd pitch -> conflict-free
    const int k = threadIdx.x;

    float ph[P];
#pragma unroll
    for (int j = 0; j < P; j++) ph[j] = phi[j];

    if (k <= P) {
#pragma unroll
        for (int i = 0; i < P; i++) h[k][i] = (k == i) ? 1.0f : 0.0f;  // k==P: zeros
        const float b0 = (k == P) ? bias[0] : 0.0f;

        float pw[8];                          // rolling window = h[k][t+40 .. t+47]
#pragma unroll
        for (int i = 0; i < 8; i++) pw[i] = h[k][40 + i];

#pragma unroll 1
        for (int t = 0; t < FLEN; t++) {
            float s0 = 0.f, s1 = 0.f, s2 = 0.f, s3 = 0.f;
#pragma unroll
            for (int j = 0; j < 40; j += 4) {           // smem terms: lag >= 5
                s0 += ph[j + 0] * h[k][t + j + 0];
                s1 += ph[j + 1] * h[k][t + j + 1];
                s2 += ph[j + 2] * h[k][t + j + 2];
                s3 += ph[j + 3] * h[k][t + j + 3];
            }
            float s = b0 + ((s0 + s1) + (s2 + s3));
#pragma unroll
            for (int i = 0; i < 8; i++) s += ph[40 + i] * pw[i];   // reg terms
            h[k][P + t] = s;
#pragma unroll
            for (int i = 0; i < 7; i++) pw[i] = pw[i + 1];
            pw[7] = s;
        }
    }
    __syncthreads();

    const float mu = *mu_p;
    const float sg = *sigma_p;

    for (int t = threadIdx.x; t < FLEN; t += blockDim.x) {
        float sum = 0.0f;
        for (int kk = 0; kk < P; kk++) sum += h[kk][P + t];
        g_C[t] = mu + sg * h[P][P + t] - mu * sum;
    }
    for (int idx = threadIdx.x; idx < P * FLEN; idx += blockDim.x) {
        const int kk = idx / FLEN;
        const int t  = idx - kk * FLEN;
        g_G[idx] = h[kk][P + t];
    }
    if (threadIdx.x == 0) g_lv = log_sigma2[0] + 2.0f * logf(sg);
}

// ---------------------------------------------------------------------------
// Kernel 2: register-blocked GEMM. 2 rows x 12 t per thread (acc = 12 ull),
// 64 rows x 84 t per CTA, 2 t-chunks, target 5 CTAs/SM (35 warps).
// Per k: 1 LDS.64 (row pair) + 3 LDS.128 (G broadcast) + 2 movs + 12 FFMA2.
// ---------------------------------------------------------------------------
#define TPB 224      // 32 row-lanes x 7 t-warps

#define YS_OFF 0                              // Ys: ull[48][32]  (12288 B)
#define GS_OFF 12288                          // Gs: float[48][84] (16128 B)
#define CS_OFF (GS_OFF + P * TCH * 4)         // Cs: float[84]
#define ML_BYTES (CS_OFF + TCH * 4)           // 28752
#define CO_BYTES (64 * 42 * 8)                // Co: ull[64][42] = 21504 (aliases)
#define SMEM_BYTES (ML_BYTES > CO_BYTES ? ML_BYTES : CO_BYTES)

__global__ void __launch_bounds__(TPB, 5)
forecast_kernel(const float* __restrict__ enc_l, float* __restrict__ out, int B) {
    __shared__ __align__(16) char smem_buf[SMEM_BYTES];
    float* YsF = (float*)(smem_buf + YS_OFF);  // slot (k, 2*(r&31)+(r>>5))
    float* Gs  = (float*)(smem_buf + GS_OFF);  // Gs[k*TCH + tt]
    float* Cs  = (float*)(smem_buf + CS_OFF);
    ull*   Co  = (ull*)smem_buf;               // epilogue restage

    const int chunk = blockIdx.x & 1;
    const int rb    = blockIdx.x >> 1;
    const int toff  = chunk * TCH;
    const int brow0 = rb * 64;

    // --- Stage G chunk + C chunk ---
    for (int i = threadIdx.x; i < P * (TCH / 4); i += TPB) {
        const int kk = i / (TCH / 4);
        const int j4 = i - kk * (TCH / 4);
        *(float4*)(Gs + kk * TCH + j4 * 4) =
            *(const float4*)(g_G + kk * FLEN + toff + j4 * 4);
    }
    if (threadIdx.x < TCH) Cs[threadIdx.x] = g_C[toff + threadIdx.x];

    // --- Stage Y: rows (r&31, r>=32) interleaved so lane tr's LDS.64 at
    // slot 2*tr yields (y[tr], y[tr+32]). ---
    for (int i = threadIdx.x; i < 64 * (P / 4); i += TPB) {
        const int r  = i / (P / 4);
        const int j4 = i - r * (P / 4);
        const int gr = brow0 + r;
        float4 v = (gr < B)
            ? *(const float4*)(enc_l + (size_t)gr * HIST + HOFF + j4 * 4)
            : make_float4(0.f, 0.f, 0.f, 0.f);
        const int slot = 2 * (r & 31) + (r >> 5);
        YsF[(4 * j4 + 0) * 64 + slot] = v.x;
        YsF[(4 * j4 + 1) * 64 + slot] = v.y;
        YsF[(4 * j4 + 2) * 64 + slot] = v.z;
        YsF[(4 * j4 + 3) * 64 + slot] = v.w;
    }
    __syncthreads();

    const int tr = threadIdx.x & 31;    // lane: rows {tr, tr+32}
    const int tc = threadIdx.x >> 5;    // warp: t = tc*12 .. +11
    const int t0 = tc * 12;

    ull acc0[6], acc1[6];
    {
        const ull* cp = (const ull*)(Cs + t0);
#pragma unroll
        for (int j = 0; j < 6; j++) { acc0[j] = cp[j]; acc1[j] = cp[j]; }
    }

    const float2* ya = (const float2*)YsF + tr;
    const ull*    ga = (const ull*)(Gs + t0);

#pragma unroll 8
    for (int k = 0; k < P; ++k) {
        const float2 av = ya[k * 32];                   // (y[tr], y[tr+32]) @ k
        const ull* gp = ga + k * (TCH / 2);             // warp-broadcast
        const ull g0 = gp[0], g1 = gp[1], g2 = gp[2],
                  g3 = gp[3], g4 = gp[4], g5 = gp[5];
        const ull y0 = pack2(av.x, av.x);
        const ull y1 = pack2(av.y, av.y);

        acc0[0] = ffma2(g0, y0, acc0[0]); acc0[1] = ffma2(g1, y0, acc0[1]);
        acc0[2] = ffma2(g2, y0, acc0[2]); acc0[3] = ffma2(g3, y0, acc0[3]);
        acc0[4] = ffma2(g4, y0, acc0[4]); acc0[5] = ffma2(g5, y0, acc0[5]);
        acc1[0] = ffma2(g0, y1, acc1[0]); acc1[1] = ffma2(g1, y1, acc1[1]);
        acc1[2] = ffma2(g2, y1, acc1[2]); acc1[3] = ffma2(g3, y1, acc1[3]);
        acc1[4] = ffma2(g4, y1, acc1[4]); acc1[5] = ffma2(g5, y1, acc1[5]);
    }

    // --- Epilogue 1: restage mu tile (Co ull[64][42], 2-way STS conflict) ---
    __syncthreads();
    {
        ull* c0 = Co + tr * 42 + tc * 6;
        ull* c1 = Co + (tr + 32) * 42 + tc * 6;
#pragma unroll
        for (int j = 0; j < 6; j++) { c0[j] = acc0[j]; c1[j] = acc1[j]; }
    }
    __syncthreads();

    // --- Epilogue 2: coalesced stores (mu + constant logvar) ---
    const float lv = g_lv;
    const float4 lv4 = make_float4(lv, lv, lv, lv);
    const size_t lvbase = (size_t)B * FLEN;
#pragma unroll 2
    for (int i = threadIdx.x; i < 64 * (TCH / 4); i += TPB) {
        const int r = i / (TCH / 4);
        const int c = i - r * (TCH / 4);
        const int gr = brow0 + r;
        if (gr < B) {
            const float4 v = *(const float4*)((const float*)Co + r * 84 + 4 * c);
            *(float4*)(out + (size_t)gr * FLEN + toff + 4 * c) = v;
            *(float4*)(out + lvbase + (size_t)gr * FLEN + toff + 4 * c) = lv4;
        }
    }
}

// ---------------------------------------------------------------------------
extern "C" void kernel_launch(void* const* d_in, const int* in_sizes, int n_in,
                              void* d_out, int out_size) {
    const float* enc_l      = (const float*)d_in[0];
    const float* phi        = (const float*)d_in[4];
    const float* bias       = (const float*)d_in[5];
    const float* log_sigma2 = (const float*)d_in[6];
    const float* mu         = (const float*)d_in[7];
    const float* sigma      = (const float*)d_in[8];

    const int B = in_sizes[0] / HIST;

    precompute_kernel<<<1, 64>>>(phi, bias, log_sigma2, mu, sigma);

    const int nblk = 2 * ((B + 63) / 64);   // x2: t-chunks of 84
    forecast_kernel<<<nblk, TPB>>>(enc_l, (float*)d_out, B);
}